// round 15
// baseline (speedup 1.0000x reference)
#include <cuda_runtime.h>
#include <cuda_fp16.h>
#include <cstdint>

// AffineCouplingLayer via legacy tensor pipe (mma.sync fp16, sm_100-safe).
// B=524288 rows, D=64. cin = even cols (32).
//   h1 = relu(cin@W1+b1); h2 = relu(h1@W2+b2); st = h2@W3+b3
//   s = tanh(st[:32]); y = x with odd cols = x_odd*exp(s)+t
// out = [ y (B*64 f32) | s (B*32 f32) ]
//
// Single-product fp16 (rel_err ~4.5e-4 < 1e-3).
// M=32 PER WARP (two m16 groups, dual independent chains) with px HELD IN
// REGISTERS for all 32 rows (no x re-read — R12/R13 proved the re-read
// toxic). TPB=128 (4 warps = 128 rows/CTA), __launch_bounds__(128,2)
// -> 256-reg cap, ~185 live regs, NO spills. 8 warps/SM.
// One ldmatrix.x4.trans feeds FOUR MMAs (2 groups x 2 j-chunks) -> LDSM
// wavefronts per row HALVED vs M=16 (L1 is the measured wall).
// Register-direct epilogue (y AND s from regs), barrier-free tile loop.
// Work-steal grid (4x resident) removes the persistent-grid tail imbalance.

#define TPB          128
#define ROWS_PER_CTA 128

// ---- SMEM layout (bytes) ----
#define WH      0            // 160 rows * 128B = 20480 (fp16 weights, SW128)
#define BIAS_O  20480        // 192 f32
#define SMEM_BYTES 21248

#define SWZ(o) ((o) ^ (((o) >> 3) & 0x70))

static __device__ __forceinline__ uint32_t smem_u32_of(const void* p) {
    uint32_t a;
    asm("{ .reg .u64 t; cvta.to.shared.u64 t, %1; cvt.u32.u64 %0, t; }" : "=r"(a) : "l"(p));
    return a;
}

static __device__ __forceinline__ uint32_t pack_f16(float lo, float hi) {
    uint32_t r;
    asm("cvt.rn.f16x2.f32 %0, %1, %2;" : "=r"(r) : "f"(hi), "f"(lo));
    return r;
}

static __device__ __forceinline__ float tanh_fast(float v) {
    return 1.0f - __fdividef(2.0f, __expf(2.0f * v) + 1.0f);
}

static __device__ __forceinline__ void mma16816(float* c, const uint32_t* a,
                                                uint32_t b0, uint32_t b1) {
    asm volatile(
        "mma.sync.aligned.m16n8k16.row.col.f32.f16.f16.f32 "
        "{%0,%1,%2,%3}, {%4,%5,%6,%7}, {%8,%9}, {%0,%1,%2,%3};"
        : "+f"(c[0]), "+f"(c[1]), "+f"(c[2]), "+f"(c[3])
        : "r"(a[0]), "r"(a[1]), "r"(a[2]), "r"(a[3]), "r"(b0), "r"(b1));
}

static __device__ __forceinline__ void ldsm4t(uint32_t addr, uint32_t* b) {
    asm volatile("ldmatrix.sync.aligned.m8n8.x4.trans.shared.b16 {%0,%1,%2,%3}, [%4];"
                 : "=r"(b[0]), "=r"(b[1]), "=r"(b[2]), "=r"(b[3]) : "r"(addr));
}

// One GEMM layer for BOTH row groups: C[mt][8][4] = A[mt] @ B.
// One ldsm.x4 per (s, j-pair) serves 4 MMAs (2 groups x 2 j-chunks).
template <int KS>
static __device__ __forceinline__ void run_layer(uint32_t base_lane, int row_rb,
                                                 const uint32_t off[4],
                                                 const uint32_t A[2][4][4],
                                                 float C[2][8][4]) {
#pragma unroll
    for (int mt = 0; mt < 2; mt++)
#pragma unroll
        for (int j = 0; j < 8; j++)
#pragma unroll
            for (int q = 0; q < 4; q++) C[mt][j][q] = 0.0f;

#pragma unroll
    for (int s = 0; s < KS; s++) {
        uint32_t base = base_lane + (uint32_t)(row_rb + s * 16) * 128;
#pragma unroll
        for (int jj = 0; jj < 4; jj++) {
            int j0 = 2 * jj, j1 = j0 + 1;
            uint32_t b[4];
            ldsm4t(base + off[jj], b);
            mma16816(C[0][j0], A[0][s], b[0], b[1]);
            mma16816(C[1][j0], A[1][s], b[0], b[1]);
            mma16816(C[0][j1], A[0][s], b[2], b[3]);
            mma16816(C[1][j1], A[1][s], b[2], b[3]);
        }
    }
}

// bias + relu + fp16 pack: C (this layer) -> A fragments (next layer)
static __device__ __forceinline__ void epi_relu_pack(const float* bias, int t4,
                                                     const float C[8][4], uint32_t A[4][4]) {
#pragma unroll
    for (int j = 0; j < 8; j++) {
        float b0 = bias[8 * j + 2 * t4];
        float b1 = bias[8 * j + 2 * t4 + 1];
        float v0 = fmaxf(C[j][0] + b0, 0.0f);
        float v1 = fmaxf(C[j][1] + b1, 0.0f);
        float v2 = fmaxf(C[j][2] + b0, 0.0f);
        float v3 = fmaxf(C[j][3] + b1, 0.0f);
        int s = j >> 1;
        int fi = (j & 1) * 2;
        A[s][fi]     = pack_f16(v0, v1);
        A[s][fi + 1] = pack_f16(v2, v3);
    }
}

__global__ void __launch_bounds__(TPB, 2)
affine_coupling_hmma(const float* __restrict__ x,
                     const float* __restrict__ W1, const float* __restrict__ b1,
                     const float* __restrict__ W2, const float* __restrict__ b2,
                     const float* __restrict__ W3, const float* __restrict__ b3,
                     float* __restrict__ out, int nrows) {
    extern __shared__ char sm[];
    const uint32_t smb = smem_u32_of(sm);

    const int tid  = threadIdx.x;
    const int wid  = tid >> 5;
    const int lane = tid & 31;
    const int g    = lane >> 2;
    const int t4   = lane & 3;
    const int lane15 = lane & 15;
    const int lanehi = (lane >> 4) & 1;       // 0: chunk j0, 1: chunk j1
    const int r0 = wid * 32 + g;              // first owned row (mt=0)

    // ---- weight prep: fp16, SW128 swizzled [k][n] rows of 128B ----
    for (int e = tid; e < 10240; e += TPB) {
        const float* src; int rel, rb;
        if (e < 2048)      { src = W1; rel = e;        rb = 0;  }
        else if (e < 6144) { src = W2; rel = e - 2048; rb = 32; }
        else               { src = W3; rel = e - 6144; rb = 96; }
        int k = rel >> 6, n = rel & 63;
        float w = __ldg(src + rel);
        uint32_t off = SWZ((uint32_t)((rb + k) * 128 + n * 2));
        *(__half*)(sm + WH + off) = __float2half_rn(w);
    }
    float* bias = (float*)(sm + BIAS_O);
    if (tid < 64) {
        bias[tid]       = __ldg(b1 + tid);
        bias[64 + tid]  = __ldg(b2 + tid);
        bias[128 + tid] = __ldg(b3 + tid);
    }
    __syncthreads();    // only barrier in the kernel

    const int ntiles = nrows / ROWS_PER_CTA;
    float* outs = out + (size_t)nrows * 64;   // s block base

    // Per-thread constant LDSM addressing (x7 loop-invariant).
    const uint32_t base_lane = smb + WH + (uint32_t)lane15 * 128;
    const int x7 = lane15 & 7;
    uint32_t off[4];
#pragma unroll
    for (int jj = 0; jj < 4; jj++)
        off[jj] = ((uint32_t)((2 * jj + lanehi) ^ x7)) << 4;

    for (int tile = blockIdx.x; tile < ntiles; tile += gridDim.x) {
        const float* xb = x + (size_t)tile * ROWS_PER_CTA * 64;

        float4 px[2][8];
        uint32_t A[2][4][4];
        float C[2][8][4];

        // ---- load x for both groups; derive layer-1 A frags (even cols) ----
#pragma unroll
        for (int mt = 0; mt < 2; mt++) {
            int rg = r0 + mt * 16;
#pragma unroll
            for (int s = 0; s < 2; s++) {
                const float4* p0 = (const float4*)(xb + rg * 64 + s * 32) + t4;
                const float4* p1 = (const float4*)(xb + (rg + 8) * 64 + s * 32) + t4;
                px[mt][s * 4 + 0] = __ldg(p0);       // row rg,   u=0
                px[mt][s * 4 + 1] = __ldg(p0 + 4);   // row rg,   u=1
                px[mt][s * 4 + 2] = __ldg(p1);       // row rg+8, u=0
                px[mt][s * 4 + 3] = __ldg(p1 + 4);   // row rg+8, u=1
                A[mt][s][0] = pack_f16(px[mt][s * 4 + 0].x, px[mt][s * 4 + 0].z);
                A[mt][s][1] = pack_f16(px[mt][s * 4 + 2].x, px[mt][s * 4 + 2].z);
                A[mt][s][2] = pack_f16(px[mt][s * 4 + 1].x, px[mt][s * 4 + 1].z);
                A[mt][s][3] = pack_f16(px[mt][s * 4 + 3].x, px[mt][s * 4 + 3].z);
            }
        }

        // ---- 3 GEMM layers, dual chains ----
        run_layer<2>(base_lane, 0, off, A, C);
        epi_relu_pack(bias, t4, C[0], A[0]);
        epi_relu_pack(bias, t4, C[1], A[1]);
        run_layer<4>(base_lane, 32, off, A, C);
        epi_relu_pack(bias + 64, t4, C[0], A[0]);
        epi_relu_pack(bias + 64, t4, C[1], A[1]);
        run_layer<4>(base_lane, 96, off, A, C);

        // ---- register-direct epilogue: y AND s straight from px + C ----
        // Block (s,u): sigma = 16s+8u+2t4; s in C[mt][2s+u][.], t in
        // C[mt][2s+u+4][.]; frag q 0,1 -> row rg, q 2,3 -> row rg+8.
        {
            const float* b3s = bias + 128;
            float4* oy = (float4*)out + (size_t)tile * (ROWS_PER_CTA * 16);
            float*  oss = outs + (size_t)tile * (ROWS_PER_CTA * 32);
#pragma unroll
            for (int mt = 0; mt < 2; mt++) {
                int rg = r0 + mt * 16;
#pragma unroll
                for (int s = 0; s < 2; s++) {
#pragma unroll
                    for (int u = 0; u < 2; u++) {
                        int js = 2 * s + u, jt = js + 4;
                        int sig = 16 * s + 8 * u + 2 * t4;
                        float bs0 = b3s[sig], bs1 = b3s[sig + 1];
                        float bt0 = b3s[32 + sig], bt1 = b3s[32 + sig + 1];

                        float sa0 = tanh_fast(C[mt][js][0] + bs0);
                        float sb0 = tanh_fast(C[mt][js][1] + bs1);
                        float sa1 = tanh_fast(C[mt][js][2] + bs0);
                        float sb1 = tanh_fast(C[mt][js][3] + bs1);
                        float ta0 = C[mt][jt][0] + bt0, tb0 = C[mt][jt][1] + bt1;
                        float ta1 = C[mt][jt][2] + bt0, tb1 = C[mt][jt][3] + bt1;

                        // s straight to global (32B-aligned chunks per warp)
                        *(float2*)(oss + (size_t)rg * 32 + sig)       = make_float2(sa0, sb0);
                        *(float2*)(oss + (size_t)(rg + 8) * 32 + sig) = make_float2(sa1, sb1);

                        // y straight from registers (no x re-read)
                        float4 v0 = px[mt][4 * s + u];          // row rg
                        float4 v1 = px[mt][4 * s + 2 + u];      // row rg+8
                        v0.y = fmaf(v0.y, __expf(sa0), ta0);
                        v0.w = fmaf(v0.w, __expf(sb0), tb0);
                        v1.y = fmaf(v1.y, __expf(sa1), ta1);
                        v1.w = fmaf(v1.w, __expf(sb1), tb1);
                        int c4 = 8 * s + 4 * u;     // float4 col index base
                        oy[rg * 16 + c4 + t4]       = v0;
                        oy[(rg + 8) * 16 + c4 + t4] = v1;
                    }
                }
            }
        }
        // no barrier: weights read-only, all outputs register-sourced
    }
}

extern "C" void kernel_launch(void* const* d_in, const int* in_sizes, int n_in,
                              void* d_out, int out_size) {
    const float* x  = (const float*)d_in[0];
    const float* W1 = (const float*)d_in[1];
    const float* b1 = (const float*)d_in[2];
    const float* W2 = (const float*)d_in[3];
    const float* b2 = (const float*)d_in[4];
    const float* W3 = (const float*)d_in[5];
    const float* b3 = (const float*)d_in[6];
    float* out = (float*)d_out;

    const int nrows = in_sizes[0] / 64;
    const int ntiles = nrows / ROWS_PER_CTA;
    int grid = 1184;                     // 4x resident (296) -> work-steal balance
    if (grid > ntiles) grid = ntiles;

    static int smem_set = 0;
    if (!smem_set) {
        cudaFuncSetAttribute(affine_coupling_hmma,
                             cudaFuncAttributeMaxDynamicSharedMemorySize, SMEM_BYTES);
        smem_set = 1;
    }
    affine_coupling_hmma<<<grid, TPB, SMEM_BYTES>>>(x, W1, b1, W2, b2, W3, b3, out, nrows);
}

// round 16
// speedup vs baseline: 1.6571x; 1.6571x over previous
#include <cuda_runtime.h>
#include <cuda_fp16.h>
#include <cstdint>

// AffineCouplingLayer via legacy tensor pipe (mma.sync fp16, sm_100-safe).
// B=524288 rows, D=64. cin = even cols (32).
//   h1 = relu(cin@W1+b1); h2 = relu(h1@W2+b2); st = h2@W3+b3
//   s = tanh(st[:32]); y = x with odd cols = x_odd*exp(s)+t
// out = [ y (B*64 f32) | s (B*32 f32) ]
//
// R16 = R10 (best: 73.8us) + cache policy + L2 prefetch:
//  - prefetch.global.L2 next tile's x (1 line/thread/tile, full tile lead)
//  - __ldcs on x (read-once streaming), __stcs on y/s (write-once) -> keep
//    L2 clean for weights + prefetched x
// Core (proven): single-product fp16 (rel_err 4.45e-4 < 1e-3); M=16/warp,
// N=64; TPB=256, 2 CTAs/SM (16 warps); activations register-resident;
// one ldmatrix.x4.trans feeds two j-chunks (lanes 0-15 j0, 16-31 j1);
// register-direct y+s epilogue; barrier-free tile loop; px held in regs
// (R12/R13 proved x re-read toxic; R15 proved 8 warps can't hide latency).

#define TPB          256
#define ROWS_PER_CTA 128

// ---- SMEM layout (bytes) ----
#define WH      0            // 160 rows * 128B = 20480 (fp16 weights, SW128)
#define BIAS_O  20480        // 192 f32
#define SMEM_BYTES 21248

#define SWZ(o) ((o) ^ (((o) >> 3) & 0x70))

static __device__ __forceinline__ uint32_t smem_u32_of(const void* p) {
    uint32_t a;
    asm("{ .reg .u64 t; cvta.to.shared.u64 t, %1; cvt.u32.u64 %0, t; }" : "=r"(a) : "l"(p));
    return a;
}

static __device__ __forceinline__ uint32_t pack_f16(float lo, float hi) {
    uint32_t r;
    asm("cvt.rn.f16x2.f32 %0, %1, %2;" : "=r"(r) : "f"(hi), "f"(lo));
    return r;
}

static __device__ __forceinline__ float tanh_fast(float v) {
    return 1.0f - __fdividef(2.0f, __expf(2.0f * v) + 1.0f);
}

static __device__ __forceinline__ void mma16816(float* c, const uint32_t* a,
                                                uint32_t b0, uint32_t b1) {
    asm volatile(
        "mma.sync.aligned.m16n8k16.row.col.f32.f16.f16.f32 "
        "{%0,%1,%2,%3}, {%4,%5,%6,%7}, {%8,%9}, {%0,%1,%2,%3};"
        : "+f"(c[0]), "+f"(c[1]), "+f"(c[2]), "+f"(c[3])
        : "r"(a[0]), "r"(a[1]), "r"(a[2]), "r"(a[3]), "r"(b0), "r"(b1));
}

static __device__ __forceinline__ void ldsm4t(uint32_t addr, uint32_t* b) {
    asm volatile("ldmatrix.sync.aligned.m8n8.x4.trans.shared.b16 {%0,%1,%2,%3}, [%4];"
                 : "=r"(b[0]), "=r"(b[1]), "=r"(b[2]), "=r"(b[3]) : "r"(addr));
}

// One GEMM layer: C[8][4] = A @ B, single fp16 product.
// One ldsm.x4 per (s, j-pair): lanes 0-15 -> chunk j0, 16-31 -> chunk j1.
template <int KS>
static __device__ __forceinline__ void run_layer(uint32_t base_lane, int row_rb,
                                                 const uint32_t off[4],
                                                 const uint32_t A[4][4], float C[8][4]) {
#pragma unroll
    for (int j = 0; j < 8; j++)
#pragma unroll
        for (int q = 0; q < 4; q++) C[j][q] = 0.0f;

#pragma unroll
    for (int s = 0; s < KS; s++) {
        uint32_t base = base_lane + (uint32_t)(row_rb + s * 16) * 128;
#pragma unroll
        for (int jj = 0; jj < 4; jj++) {
            uint32_t b[4];
            ldsm4t(base + off[jj], b);
            mma16816(C[2 * jj],     A[s], b[0], b[1]);
            mma16816(C[2 * jj + 1], A[s], b[2], b[3]);
        }
    }
}

// bias + relu + fp16 pack: C (this layer) -> A fragments (next layer)
static __device__ __forceinline__ void epi_relu_pack(const float* bias, int t4,
                                                     const float C[8][4], uint32_t A[4][4]) {
#pragma unroll
    for (int j = 0; j < 8; j++) {
        float b0 = bias[8 * j + 2 * t4];
        float b1 = bias[8 * j + 2 * t4 + 1];
        float v0 = fmaxf(C[j][0] + b0, 0.0f);
        float v1 = fmaxf(C[j][1] + b1, 0.0f);
        float v2 = fmaxf(C[j][2] + b0, 0.0f);
        float v3 = fmaxf(C[j][3] + b1, 0.0f);
        int s = j >> 1;
        int fi = (j & 1) * 2;
        A[s][fi]     = pack_f16(v0, v1);
        A[s][fi + 1] = pack_f16(v2, v3);
    }
}

// Gather layer-1 A fragments from the 8 live px float4 (even cols of x).
static __device__ __forceinline__ void frags_from_x(const float4 px[8], uint32_t A[4][4]) {
#pragma unroll
    for (int s = 0; s < 2; s++) {
        const float4& f0 = px[s * 4 + 0];   // row r0,   col-half u=0
        const float4& f1 = px[s * 4 + 1];   // row r0,   col-half u=1
        const float4& f2 = px[s * 4 + 2];   // row r0+8, u=0
        const float4& f3 = px[s * 4 + 3];   // row r0+8, u=1
        A[s][0] = pack_f16(f0.x, f0.z);
        A[s][1] = pack_f16(f2.x, f2.z);
        A[s][2] = pack_f16(f1.x, f1.z);
        A[s][3] = pack_f16(f3.x, f3.z);
    }
}

// Streaming (evict-first) x loads: read-once data, keep L2 for weights.
static __device__ __forceinline__ void load_px(const float* xb, int r0, int t4, float4 px[8]) {
#pragma unroll
    for (int s = 0; s < 2; s++) {
        const float4* p0 = (const float4*)(xb + r0 * 64 + s * 32) + t4;
        const float4* p1 = (const float4*)(xb + (r0 + 8) * 64 + s * 32) + t4;
        px[s * 4 + 0] = __ldcs(p0);
        px[s * 4 + 1] = __ldcs(p0 + 4);
        px[s * 4 + 2] = __ldcs(p1);
        px[s * 4 + 3] = __ldcs(p1 + 4);
    }
}

__global__ void __launch_bounds__(TPB, 2)
affine_coupling_hmma(const float* __restrict__ x,
                     const float* __restrict__ W1, const float* __restrict__ b1,
                     const float* __restrict__ W2, const float* __restrict__ b2,
                     const float* __restrict__ W3, const float* __restrict__ b3,
                     float* __restrict__ out, int nrows) {
    extern __shared__ char sm[];
    const uint32_t smb = smem_u32_of(sm);

    const int tid  = threadIdx.x;
    const int wid  = tid >> 5;
    const int lane = tid & 31;
    const int g    = lane >> 2;
    const int t4   = lane & 3;
    const int lane15 = lane & 15;
    const int lanehi = (lane >> 4) & 1;       // 0: chunk j0, 1: chunk j1
    const int r0 = wid * 16 + g;              // first owned row

    // ---- weight prep: fp16, SW128 swizzled [k][n] rows of 128B ----
    for (int e = tid; e < 10240; e += TPB) {
        const float* src; int rel, rb;
        if (e < 2048)      { src = W1; rel = e;        rb = 0;  }
        else if (e < 6144) { src = W2; rel = e - 2048; rb = 32; }
        else               { src = W3; rel = e - 6144; rb = 96; }
        int k = rel >> 6, n = rel & 63;
        float w = __ldg(src + rel);
        uint32_t off = SWZ((uint32_t)((rb + k) * 128 + n * 2));
        *(__half*)(sm + WH + off) = __float2half_rn(w);
    }
    float* bias = (float*)(sm + BIAS_O);
    if (tid < 64) {
        bias[tid]       = __ldg(b1 + tid);
        bias[64 + tid]  = __ldg(b2 + tid);
        bias[128 + tid] = __ldg(b3 + tid);
    }
    __syncthreads();    // only barrier in the kernel

    const int ntiles = nrows / ROWS_PER_CTA;
    float* outs = out + (size_t)nrows * 64;   // s block base

    // Per-thread constant LDSM addressing (x7 loop-invariant).
    const uint32_t base_lane = smb + WH + (uint32_t)lane15 * 128;
    const int x7 = lane15 & 7;
    uint32_t off[4];
#pragma unroll
    for (int jj = 0; jj < 4; jj++)
        off[jj] = ((uint32_t)((2 * jj + lanehi) ^ x7)) << 4;

    for (int tile = blockIdx.x; tile < ntiles; tile += gridDim.x) {
        const float* xb = x + (size_t)tile * ROWS_PER_CTA * 64;

        float4 px[8];
        load_px(xb, r0, t4, px);

        // ---- L2 prefetch of NEXT tile's x: 1 line (128B) per thread ----
        {
            int tn = tile + gridDim.x;
            if (tn < ntiles) {
                const float* pn = x + (size_t)tn * ROWS_PER_CTA * 64 + (size_t)tid * 32;
                asm volatile("prefetch.global.L2 [%0];" :: "l"(pn));
            }
        }

        uint32_t A[4][4];
        float C[8][4];

        frags_from_x(px, A);

        // ---- 3 GEMM layers ----
        run_layer<2>(base_lane, 0,  off, A, C);
        epi_relu_pack(bias, t4, C, A);
        run_layer<4>(base_lane, 32, off, A, C);
        epi_relu_pack(bias + 64, t4, C, A);
        run_layer<4>(base_lane, 96, off, A, C);

        // ---- register-direct epilogue: y AND s straight from px + C ----
        // Block (s,u): sigma = 16s+8u+2t4; s in C[2s+u][.], t in C[2s+u+4][.];
        // frag q 0,1 -> row r0, q 2,3 -> row r0+8. Streaming stores (.cs).
        {
            const float* b3s = bias + 128;
            float4* oy = (float4*)out + (size_t)tile * (ROWS_PER_CTA * 16);
            float*  oss = outs + (size_t)tile * (ROWS_PER_CTA * 32);
#pragma unroll
            for (int s = 0; s < 2; s++) {
#pragma unroll
                for (int u = 0; u < 2; u++) {
                    int js = 2 * s + u, jt = js + 4;
                    int sig = 16 * s + 8 * u + 2 * t4;
                    float bs0 = b3s[sig], bs1 = b3s[sig + 1];
                    float bt0 = b3s[32 + sig], bt1 = b3s[32 + sig + 1];

                    float sa0 = tanh_fast(C[js][0] + bs0);
                    float sb0 = tanh_fast(C[js][1] + bs1);
                    float sa1 = tanh_fast(C[js][2] + bs0);
                    float sb1 = tanh_fast(C[js][3] + bs1);
                    float ta0 = C[jt][0] + bt0, tb0 = C[jt][1] + bt1;
                    float ta1 = C[jt][2] + bt0, tb1 = C[jt][3] + bt1;

                    // s straight to global (32B-aligned chunks per warp)
                    __stcs((float2*)(oss + (size_t)r0 * 32 + sig),       make_float2(sa0, sb0));
                    __stcs((float2*)(oss + (size_t)(r0 + 8) * 32 + sig), make_float2(sa1, sb1));

                    // y straight from registers
                    float4 v0 = px[4 * s + u];          // row r0
                    float4 v1 = px[4 * s + 2 + u];      // row r0+8
                    v0.y = fmaf(v0.y, __expf(sa0), ta0);
                    v0.w = fmaf(v0.w, __expf(sb0), tb0);
                    v1.y = fmaf(v1.y, __expf(sa1), ta1);
                    v1.w = fmaf(v1.w, __expf(sb1), tb1);
                    int c4 = 8 * s + 4 * u;     // float4 col index base
                    __stcs(&oy[r0 * 16 + c4 + t4],       v0);
                    __stcs(&oy[(r0 + 8) * 16 + c4 + t4], v1);
                }
            }
        }
        // no barrier: weights read-only, all outputs register-sourced
    }
}

extern "C" void kernel_launch(void* const* d_in, const int* in_sizes, int n_in,
                              void* d_out, int out_size) {
    const float* x  = (const float*)d_in[0];
    const float* W1 = (const float*)d_in[1];
    const float* b1 = (const float*)d_in[2];
    const float* W2 = (const float*)d_in[3];
    const float* b2 = (const float*)d_in[4];
    const float* W3 = (const float*)d_in[5];
    const float* b3 = (const float*)d_in[6];
    float* out = (float*)d_out;

    const int nrows = in_sizes[0] / 64;
    const int ntiles = nrows / ROWS_PER_CTA;
    int grid = 296;                      // 2 CTAs/SM * 148 SMs, persistent
    if (grid > ntiles) grid = ntiles;

    static int smem_set = 0;
    if (!smem_set) {
        cudaFuncSetAttribute(affine_coupling_hmma,
                             cudaFuncAttributeMaxDynamicSharedMemorySize, SMEM_BYTES);
        smem_set = 1;
    }
    affine_coupling_hmma<<<grid, TPB, SMEM_BYTES>>>(x, W1, b1, W2, b2, W3, b3, out, nrows);
}

// round 17
// speedup vs baseline: 1.7067x; 1.0299x over previous
#include <cuda_runtime.h>
#include <cuda_fp16.h>
#include <cstdint>

// AffineCouplingLayer via legacy tensor pipe (mma.sync fp16, sm_100-safe).
// B=524288 rows, D=64. cin = even cols (32).
//   h1 = relu(cin@W1+b1); h2 = relu(h1@W2+b2); st = h2@W3+b3
//   s = tanh(st[:32]); y = x with odd cols = x_odd*exp(s)+t
// out = [ y (B*64 f32) | s (B*32 f32) ]
//
// R17 = R16 (best: 71.7us) + ALU trim:
//  - per-thread global base pointers hoisted out of the tile loop, advanced
//    by constant strides (3 pointer adds/tile vs ~20 IMAD chains)
//  - epilogue restructured compute-then-store (all MUFU before any STG)
// Core (proven): single-product fp16 (rel_err 4.45e-4); M=16/warp, N=64;
// TPB=256, 2 CTAs/SM (16 warps); activations register-resident; one
// ldmatrix.x4.trans per 2 MMAs (HW minimum); px held in regs; register-
// direct y+s epilogue; barrier-free tile loop; __ldcs/__stcs streaming;
// L2 prefetch of next tile's x.

#define TPB          256
#define ROWS_PER_CTA 128

// ---- SMEM layout (bytes) ----
#define WH      0            // 160 rows * 128B = 20480 (fp16 weights, SW128)
#define BIAS_O  20480        // 192 f32
#define SMEM_BYTES 21248

#define SWZ(o) ((o) ^ (((o) >> 3) & 0x70))

static __device__ __forceinline__ uint32_t smem_u32_of(const void* p) {
    uint32_t a;
    asm("{ .reg .u64 t; cvta.to.shared.u64 t, %1; cvt.u32.u64 %0, t; }" : "=r"(a) : "l"(p));
    return a;
}

static __device__ __forceinline__ uint32_t pack_f16(float lo, float hi) {
    uint32_t r;
    asm("cvt.rn.f16x2.f32 %0, %1, %2;" : "=r"(r) : "f"(hi), "f"(lo));
    return r;
}

static __device__ __forceinline__ float tanh_fast(float v) {
    return 1.0f - __fdividef(2.0f, __expf(2.0f * v) + 1.0f);
}

static __device__ __forceinline__ void mma16816(float* c, const uint32_t* a,
                                                uint32_t b0, uint32_t b1) {
    asm volatile(
        "mma.sync.aligned.m16n8k16.row.col.f32.f16.f16.f32 "
        "{%0,%1,%2,%3}, {%4,%5,%6,%7}, {%8,%9}, {%0,%1,%2,%3};"
        : "+f"(c[0]), "+f"(c[1]), "+f"(c[2]), "+f"(c[3])
        : "r"(a[0]), "r"(a[1]), "r"(a[2]), "r"(a[3]), "r"(b0), "r"(b1));
}

static __device__ __forceinline__ void ldsm4t(uint32_t addr, uint32_t* b) {
    asm volatile("ldmatrix.sync.aligned.m8n8.x4.trans.shared.b16 {%0,%1,%2,%3}, [%4];"
                 : "=r"(b[0]), "=r"(b[1]), "=r"(b[2]), "=r"(b[3]) : "r"(addr));
}

// One GEMM layer: C[8][4] = A @ B, single fp16 product.
// One ldsm.x4 per (s, j-pair): lanes 0-15 -> chunk j0, 16-31 -> chunk j1.
template <int KS>
static __device__ __forceinline__ void run_layer(uint32_t base_lane, int row_rb,
                                                 const uint32_t off[4],
                                                 const uint32_t A[4][4], float C[8][4]) {
#pragma unroll
    for (int j = 0; j < 8; j++)
#pragma unroll
        for (int q = 0; q < 4; q++) C[j][q] = 0.0f;

#pragma unroll
    for (int s = 0; s < KS; s++) {
        uint32_t base = base_lane + (uint32_t)(row_rb + s * 16) * 128;
#pragma unroll
        for (int jj = 0; jj < 4; jj++) {
            uint32_t b[4];
            ldsm4t(base + off[jj], b);
            mma16816(C[2 * jj],     A[s], b[0], b[1]);
            mma16816(C[2 * jj + 1], A[s], b[2], b[3]);
        }
    }
}

// bias + relu + fp16 pack: C (this layer) -> A fragments (next layer)
static __device__ __forceinline__ void epi_relu_pack(const float* bias, int t4,
                                                     const float C[8][4], uint32_t A[4][4]) {
#pragma unroll
    for (int j = 0; j < 8; j++) {
        float b0 = bias[8 * j + 2 * t4];
        float b1 = bias[8 * j + 2 * t4 + 1];
        float v0 = fmaxf(C[j][0] + b0, 0.0f);
        float v1 = fmaxf(C[j][1] + b1, 0.0f);
        float v2 = fmaxf(C[j][2] + b0, 0.0f);
        float v3 = fmaxf(C[j][3] + b1, 0.0f);
        int s = j >> 1;
        int fi = (j & 1) * 2;
        A[s][fi]     = pack_f16(v0, v1);
        A[s][fi + 1] = pack_f16(v2, v3);
    }
}

// Gather layer-1 A fragments from the 8 live px float4 (even cols of x).
static __device__ __forceinline__ void frags_from_x(const float4 px[8], uint32_t A[4][4]) {
#pragma unroll
    for (int s = 0; s < 2; s++) {
        const float4& f0 = px[s * 4 + 0];   // row r0,   col-half u=0
        const float4& f1 = px[s * 4 + 1];   // row r0,   col-half u=1
        const float4& f2 = px[s * 4 + 2];   // row r0+8, u=0
        const float4& f3 = px[s * 4 + 3];   // row r0+8, u=1
        A[s][0] = pack_f16(f0.x, f0.z);
        A[s][1] = pack_f16(f2.x, f2.z);
        A[s][2] = pack_f16(f1.x, f1.z);
        A[s][3] = pack_f16(f3.x, f3.z);
    }
}

__global__ void __launch_bounds__(TPB, 2)
affine_coupling_hmma(const float* __restrict__ x,
                     const float* __restrict__ W1, const float* __restrict__ b1,
                     const float* __restrict__ W2, const float* __restrict__ b2,
                     const float* __restrict__ W3, const float* __restrict__ b3,
                     float* __restrict__ out, int nrows) {
    extern __shared__ char sm[];
    const uint32_t smb = smem_u32_of(sm);

    const int tid  = threadIdx.x;
    const int wid  = tid >> 5;
    const int lane = tid & 31;
    const int g    = lane >> 2;
    const int t4   = lane & 3;
    const int lane15 = lane & 15;
    const int lanehi = (lane >> 4) & 1;       // 0: chunk j0, 1: chunk j1
    const int r0 = wid * 16 + g;              // first owned row

    // ---- weight prep: fp16, SW128 swizzled [k][n] rows of 128B ----
    for (int e = tid; e < 10240; e += TPB) {
        const float* src; int rel, rb;
        if (e < 2048)      { src = W1; rel = e;        rb = 0;  }
        else if (e < 6144) { src = W2; rel = e - 2048; rb = 32; }
        else               { src = W3; rel = e - 6144; rb = 96; }
        int k = rel >> 6, n = rel & 63;
        float w = __ldg(src + rel);
        uint32_t off = SWZ((uint32_t)((rb + k) * 128 + n * 2));
        *(__half*)(sm + WH + off) = __float2half_rn(w);
    }
    float* bias = (float*)(sm + BIAS_O);
    if (tid < 64) {
        bias[tid]       = __ldg(b1 + tid);
        bias[64 + tid]  = __ldg(b2 + tid);
        bias[128 + tid] = __ldg(b3 + tid);
    }
    __syncthreads();    // only barrier in the kernel

    const int ntiles = nrows / ROWS_PER_CTA;

    // Per-thread constant LDSM addressing (x7 loop-invariant).
    const uint32_t base_lane = smb + WH + (uint32_t)lane15 * 128;
    const int x7 = lane15 & 7;
    uint32_t off[4];
#pragma unroll
    for (int jj = 0; jj < 4; jj++)
        off[jj] = ((uint32_t)((2 * jj + lanehi) ^ x7)) << 4;

    // Per-thread global base pointers, advanced by constant strides per tile.
    const size_t tile_f4  = (size_t)ROWS_PER_CTA * 16;           // float4 per tile (y/x)
    const size_t step_f4  = (size_t)gridDim.x * tile_f4;
    const size_t step_s   = (size_t)gridDim.x * ROWS_PER_CTA * 32;
    const float4* xp = (const float4*)x + (size_t)blockIdx.x * tile_f4 + (size_t)r0 * 16 + t4;
    float4*       yp = (float4*)out     + (size_t)blockIdx.x * tile_f4 + (size_t)r0 * 16 + t4;
    float*        sp = out + (size_t)nrows * 64
                      + (size_t)blockIdx.x * ROWS_PER_CTA * 32 + (size_t)r0 * 32 + 2 * t4;
    const char*   pf = (const char*)x
                      + ((size_t)blockIdx.x * tile_f4 + (size_t)tid * 2) * 16;  // tid*32 floats

    for (int tile = blockIdx.x; tile < ntiles;
         tile += gridDim.x, xp += step_f4, yp += step_f4, sp += step_s,
         pf += step_f4 * 16) {

        // ---- streaming px load (read-once) ----
        float4 px[8];
#pragma unroll
        for (int s = 0; s < 2; s++) {
            px[s * 4 + 0] = __ldcs(xp + 8 * s);          // row r0,   u=0
            px[s * 4 + 1] = __ldcs(xp + 8 * s + 4);      // row r0,   u=1
            px[s * 4 + 2] = __ldcs(xp + 8 * s + 128);    // row r0+8, u=0
            px[s * 4 + 3] = __ldcs(xp + 8 * s + 132);    // row r0+8, u=1
        }

        // ---- L2 prefetch of NEXT tile's x: 1 line (128B) per thread ----
        if (tile + (int)gridDim.x < ntiles)
            asm volatile("prefetch.global.L2 [%0];" :: "l"(pf + step_f4 * 16));

        uint32_t A[4][4];
        float C[8][4];

        frags_from_x(px, A);

        // ---- 3 GEMM layers ----
        run_layer<2>(base_lane, 0,  off, A, C);
        epi_relu_pack(bias, t4, C, A);
        run_layer<4>(base_lane, 32, off, A, C);
        epi_relu_pack(bias + 64, t4, C, A);
        run_layer<4>(base_lane, 96, off, A, C);

        // ---- register-direct epilogue, compute-then-store ----
        // Block (s,u): sigma = 16s+8u+2t4; s in C[2s+u][.], t in C[2s+u+4][.];
        // frag q 0,1 -> row r0, q 2,3 -> row r0+8.
        {
            const float* b3s = bias + 128;
            float sa[2][2][2], sb[2][2][2];       // [s][u][row-half]
            float ea[2][2][2], eb[2][2][2];

            // pass 1: all tanh
#pragma unroll
            for (int s = 0; s < 2; s++)
#pragma unroll
                for (int u = 0; u < 2; u++) {
                    int js = 2 * s + u;
                    int sig = 16 * s + 8 * u + 2 * t4;
                    float bs0 = b3s[sig], bs1 = b3s[sig + 1];
                    sa[s][u][0] = tanh_fast(C[js][0] + bs0);
                    sb[s][u][0] = tanh_fast(C[js][1] + bs1);
                    sa[s][u][1] = tanh_fast(C[js][2] + bs0);
                    sb[s][u][1] = tanh_fast(C[js][3] + bs1);
                }
            // pass 2: all exp
#pragma unroll
            for (int s = 0; s < 2; s++)
#pragma unroll
                for (int u = 0; u < 2; u++) {
                    ea[s][u][0] = __expf(sa[s][u][0]);
                    eb[s][u][0] = __expf(sb[s][u][0]);
                    ea[s][u][1] = __expf(sa[s][u][1]);
                    eb[s][u][1] = __expf(sb[s][u][1]);
                }
            // pass 3: stores (streaming)
#pragma unroll
            for (int s = 0; s < 2; s++)
#pragma unroll
                for (int u = 0; u < 2; u++) {
                    int jt = 2 * s + u + 4;
                    int sig = 16 * s + 8 * u;
                    float bt0 = b3s[32 + sig + 2 * t4], bt1 = b3s[32 + sig + 2 * t4 + 1];

                    __stcs((float2*)(sp + sig),       make_float2(sa[s][u][0], sb[s][u][0]));
                    __stcs((float2*)(sp + 256 + sig), make_float2(sa[s][u][1], sb[s][u][1]));

                    float4 v0 = px[4 * s + u];          // row r0
                    float4 v1 = px[4 * s + 2 + u];      // row r0+8
                    v0.y = fmaf(v0.y, ea[s][u][0], C[jt][0] + bt0);
                    v0.w = fmaf(v0.w, eb[s][u][0], C[jt][1] + bt1);
                    v1.y = fmaf(v1.y, ea[s][u][1], C[jt][2] + bt0);
                    v1.w = fmaf(v1.w, eb[s][u][1], C[jt][3] + bt1);
                    __stcs(yp + 8 * s + 4 * u,       v0);
                    __stcs(yp + 8 * s + 4 * u + 128, v1);
                }
        }
        // no barrier: weights read-only, all outputs register-sourced
    }
}

extern "C" void kernel_launch(void* const* d_in, const int* in_sizes, int n_in,
                              void* d_out, int out_size) {
    const float* x  = (const float*)d_in[0];
    const float* W1 = (const float*)d_in[1];
    const float* b1 = (const float*)d_in[2];
    const float* W2 = (const float*)d_in[3];
    const float* b2 = (const float*)d_in[4];
    const float* W3 = (const float*)d_in[5];
    const float* b3 = (const float*)d_in[6];
    float* out = (float*)d_out;

    const int nrows = in_sizes[0] / 64;
    const int ntiles = nrows / ROWS_PER_CTA;
    int grid = 296;                      // 2 CTAs/SM * 148 SMs, persistent
    if (grid > ntiles) grid = ntiles;

    static int smem_set = 0;
    if (!smem_set) {
        cudaFuncSetAttribute(affine_coupling_hmma,
                             cudaFuncAttributeMaxDynamicSharedMemorySize, SMEM_BYTES);
        smem_set = 1;
    }
    affine_coupling_hmma<<<grid, TPB, SMEM_BYTES>>>(x, W1, b1, W2, b2, W3, b3, out, nrows);
}